// round 16
// baseline (speedup 1.0000x reference)
#include <cuda_runtime.h>
#include <cuda_bf16.h>
#include <float.h>
#include <stdint.h>

#define DIM            300
#define DIM4           75                        // float4 per row
#define ROWB           (DIM * 4)                 // 1200 bytes per row
#define MAXK           16
#define TPB            256                       // 8 warps
#define WPB            (TPB / 32)
#define NBH            148                       // blocks per path
#define NB             (2 * NBH)                 // 2 CTAs per SM, one per path
#define AHEAD          4                         // LDG-path prefetch lead (pairs)
#define ROWS_PER_STAGE 16                        // TMA-path stage rows
#define STAGE_BYTES    (ROWS_PER_STAGE * ROWB)   // 19200
#define STAGE_F4       (ROWS_PER_STAGE * DIM4)   // 1200 float4
#define NSTAGES        5
#define SMEM_BYTES     (NSTAGES * STAGE_BYTES)   // 96000 per CTA

// Scratch (allocation-free rule: __device__ globals)
__device__ float        g_cand_v[NB * MAXK];
__device__ int          g_cand_i[NB * MAXK];
__device__ unsigned int g_done = 0;

// ---------------------------------------------------------------------------
// PTX helpers
// ---------------------------------------------------------------------------
__device__ __forceinline__ unsigned smem_u32(const void* p)
{
    return (unsigned)__cvta_generic_to_shared(p);
}
__device__ __forceinline__ void mbar_init(unsigned mbar, unsigned count)
{
    asm volatile("mbarrier.init.shared.b64 [%0], %1;" :: "r"(mbar), "r"(count) : "memory");
}
__device__ __forceinline__ void mbar_expect_tx(unsigned mbar, unsigned bytes)
{
    asm volatile("mbarrier.arrive.expect_tx.shared.b64 _, [%0], %1;"
                 :: "r"(mbar), "r"(bytes) : "memory");
}
__device__ __forceinline__ void mbar_wait(unsigned mbar, unsigned phase)
{
    unsigned done;
    asm volatile("{\n\t.reg .pred p;\n\t"
                 "mbarrier.try_wait.parity.shared.b64 p, [%1], %2;\n\t"
                 "selp.b32 %0, 1, 0, p;\n\t}"
                 : "=r"(done) : "r"(mbar), "r"(phase) : "memory");
    if (!done) {
        asm volatile("{\n\t.reg .pred P1;\n\t"
                     "W_%=:\n\t"
                     "mbarrier.try_wait.parity.shared.b64 P1, [%0], %1, 0x989680;\n\t"
                     "@P1 bra.uni D_%=;\n\t"
                     "bra.uni W_%=;\n\t"
                     "D_%=:\n\t}"
                     :: "r"(mbar), "r"(phase) : "memory");
    }
}
__device__ __forceinline__ void bulk_g2s(unsigned dst, const void* src,
                                         unsigned bytes, unsigned mbar)
{
    asm volatile("cp.async.bulk.shared::cta.global.mbarrier::complete_tx::bytes "
                 "[%0], [%1], %2, [%3];"
                 :: "r"(dst), "l"(src), "r"(bytes), "r"(mbar) : "memory");
}
__device__ __forceinline__ void bulk_prefetch_l2(const void* src, unsigned bytes)
{
    asm volatile("cp.async.bulk.prefetch.L2.global [%0], %1;"
                 :: "l"(src), "r"(bytes) : "memory");
}
__device__ __forceinline__ void fence_async_smem()
{
    asm volatile("fence.proxy.async.shared::cta;" ::: "memory");
}

// ---------------------------------------------------------------------------
// top-K helpers (ascending-sorted register list; slot 0 = current min)
// ---------------------------------------------------------------------------
__device__ __forceinline__ void topk_insert(float* vals, int* ids, int K,
                                            float s, int id)
{
    if (s > vals[0] || (s == vals[0] && id < ids[0])) {
        int j = 0;
        while (j < K - 1 &&
               (s > vals[j + 1] || (s == vals[j + 1] && id < ids[j + 1]))) {
            vals[j] = vals[j + 1];
            ids [j] = ids [j + 1];
            j++;
        }
        vals[j] = s;
        ids [j] = id;
    }
}

#define WARP_EXTRACT_TOPK(vals, ids, K, EMIT)                                  \
    do {                                                                       \
        int ptr = (K) - 1;                                                     \
        for (int r = 0; r < (K); r++) {                                        \
            float v  = (ptr >= 0) ? (vals)[ptr] : -FLT_MAX;                    \
            int   id = (ptr >= 0) ? (ids)[ptr]  : 0x7fffffff;                  \
            float bv = v; int bid = id; int bl = lane;                         \
            _Pragma("unroll")                                                  \
            for (int off = 16; off; off >>= 1) {                               \
                float ov  = __shfl_xor_sync(0xffffffffu, bv,  off);            \
                int   oid = __shfl_xor_sync(0xffffffffu, bid, off);            \
                int   ol  = __shfl_xor_sync(0xffffffffu, bl,  off);            \
                if (ov > bv || (ov == bv && oid < bid)) {                      \
                    bv = ov; bid = oid; bl = ol;                               \
                }                                                              \
            }                                                                  \
            if (lane == bl) ptr--;                                             \
            if (lane == 0) { EMIT; }                                           \
        }                                                                      \
    } while (0)

__device__ __forceinline__ float dot_row(const float4* __restrict__ rp,
                                         int lane,
                                         float4 b0, float4 b1, float4 b2)
{
    float4 a0 = rp[lane];
    float4 a1 = rp[lane + 32];
    float acc = a0.x * b0.x + a0.y * b0.y + a0.z * b0.z + a0.w * b0.w
              + a1.x * b1.x + a1.y * b1.y + a1.z * b1.z + a1.w * b1.w;
    if (lane < DIM4 - 64) {
        float4 a2 = rp[lane + 64];
        acc += a2.x * b2.x + a2.y * b2.y + a2.z * b2.z + a2.w * b2.w;
    }
    return acc;
}
__device__ __forceinline__ float warp_sum(float acc)
{
#pragma unroll
    for (int off = 16; off; off >>= 1)
        acc += __shfl_xor_sync(0xffffffffu, acc, off);
    return acc;
}
// two rows with interleaved reduction chains
__device__ __forceinline__ void dot2(const float4* __restrict__ r0p,
                                     const float4* __restrict__ r1p,
                                     int lane, float4 b0, float4 b1, float4 b2,
                                     float& s0, float& s1)
{
    float4 a0 = r0p[lane],      a1 = r1p[lane];
    float4 c0 = r0p[lane + 32], c1 = r1p[lane + 32];
    s0 = a0.x*b0.x + a0.y*b0.y + a0.z*b0.z + a0.w*b0.w
       + c0.x*b1.x + c0.y*b1.y + c0.z*b1.z + c0.w*b1.w;
    s1 = a1.x*b0.x + a1.y*b0.y + a1.z*b0.z + a1.w*b0.w
       + c1.x*b1.x + c1.y*b1.y + c1.z*b1.z + c1.w*b1.w;
    if (lane < DIM4 - 64) {
        float4 d0 = r0p[lane + 64], d1 = r1p[lane + 64];
        s0 += d0.x*b2.x + d0.y*b2.y + d0.z*b2.z + d0.w*b2.w;
        s1 += d1.x*b2.x + d1.y*b2.y + d1.z*b2.z + d1.w*b2.w;
    }
#pragma unroll
    for (int off = 16; off; off >>= 1) {
        s0 += __shfl_xor_sync(0xffffffffu, s0, off);
        s1 += __shfl_xor_sync(0xffffffffu, s1, off);
    }
}

// ---------------------------------------------------------------------------
// Fused persistent kernel: per-CTA dual path.
//   blocks [0, NBH)      : LDG demand + TMA bulk-prefetch-to-L2 (R12 form)
//   blocks [NBH, 2*NBH)  : TMA-bulk smem ring demand (R8 form)
// Classic placement puts block b and b+148 on the same SM -> each SM runs
// one CTA of each path concurrently.
// ---------------------------------------------------------------------------
__global__ void __launch_bounds__(TPB, 2)
fused_sim_topk_kernel(const int* __restrict__ wordid,
                      const float* __restrict__ emb,
                      float* __restrict__ out,
                      int V, int K)
{
    extern __shared__ float4 sbuf[];
    __shared__ float4 swv[DIM4];
    __shared__ float  sv[WPB * MAXK];
    __shared__ int    si[WPB * MAXK];
    __shared__ int    s_last;
    __shared__ __align__(8) unsigned long long mbar_full[NSTAGES];

    const int tid  = threadIdx.x;
    const int lane = tid & 31;
    const int warp = tid >> 5;
    const bool is_tma = (blockIdx.x >= NBH);

    if (tid == 0) {
#pragma unroll
        for (int s = 0; s < NSTAGES; s++)
            mbar_init(smem_u32(&mbar_full[s]), 1);
        fence_async_smem();
    }
    {
        int w = wordid[0];
        if (tid < DIM4)
            swv[tid] = reinterpret_cast<const float4*>(emb + (size_t)w * DIM)[tid];
    }
    __syncthreads();

    const float4 b0 = swv[lane];
    const float4 b1 = swv[lane + 32];
    const float4 b2 = (lane < DIM4 - 64) ? swv[lane + 64]
                                         : make_float4(0.f, 0.f, 0.f, 0.f);

    // --- this block's contiguous row chunk ---
    const int chunk    = (V + NB - 1) / NB;
    const int row_base = blockIdx.x * chunk;
    int rows_blk = V - row_base;
    if (rows_blk > chunk) rows_blk = chunk;
    if (rows_blk < 0)     rows_blk = 0;
    const int row_end = row_base + rows_blk;

    const float4* emb4 = reinterpret_cast<const float4*>(emb);
    const char*   embc = reinterpret_cast<const char*>(emb);

    // --- per-warp running top-K (lane 0 holds it) ---
    float vals[MAXK];
    int   ids [MAXK];
#pragma unroll
    for (int j = 0; j < MAXK; j++) { vals[j] = -FLT_MAX; ids[j] = 0x7fffffff; }

    if (is_tma) {
        // ================= TMA smem-ring path (R8) =========================
        const int ntiles = (rows_blk + ROWS_PER_STAGE - 1) / ROWS_PER_STAGE;
        const char* gbase = embc + (size_t)row_base * ROWB;
        const unsigned sbase = smem_u32(sbuf);

        if (tid == 0) {
            int np = (ntiles < NSTAGES) ? ntiles : NSTAGES;
            for (int s = 0; s < np; s++) {
                int rows_v = rows_blk - s * ROWS_PER_STAGE;
                if (rows_v > ROWS_PER_STAGE) rows_v = ROWS_PER_STAGE;
                unsigned bytes = (unsigned)rows_v * ROWB;
                unsigned mb = smem_u32(&mbar_full[s]);
                unsigned bh = bytes / 2;
                mbar_expect_tx(mb, bytes);
                bulk_g2s(sbase + s * STAGE_BYTES,
                         gbase + (size_t)s * STAGE_BYTES, bh, mb);
                bulk_g2s(sbase + s * STAGE_BYTES + bh,
                         gbase + (size_t)s * STAGE_BYTES + bh, bytes - bh, mb);
            }
        }

        int slot = 0, phase = 0;
        for (int s = 0; s < ntiles; s++) {
            mbar_wait(smem_u32(&mbar_full[slot]), phase);

            int rows_v = rows_blk - s * ROWS_PER_STAGE;
            if (rows_v > ROWS_PER_STAGE) rows_v = ROWS_PER_STAGE;
            const float4* buf = sbuf + slot * STAGE_F4;
            const int rb = row_base + s * ROWS_PER_STAGE;

            if (rows_v == ROWS_PER_STAGE) {
                float s0, s1;
                dot2(buf + warp * DIM4, buf + (warp + WPB) * DIM4,
                     lane, b0, b1, b2, s0, s1);
                if (lane == 0) {
                    topk_insert(vals, ids, K, s0, rb + warp);
                    topk_insert(vals, ids, K, s1, rb + warp + WPB);
                }
            } else {
                for (int r = warp; r < rows_v; r += WPB) {
                    float acc = warp_sum(dot_row(buf + r * DIM4, lane, b0, b1, b2));
                    if (lane == 0) topk_insert(vals, ids, K, acc, rb + r);
                }
            }
            __syncthreads();

            const int ns = s + NSTAGES;
            if (tid == 0 && ns < ntiles) {
                int rows_n = rows_blk - ns * ROWS_PER_STAGE;
                if (rows_n > ROWS_PER_STAGE) rows_n = ROWS_PER_STAGE;
                unsigned bytes = (unsigned)rows_n * ROWB;
                unsigned mb = smem_u32(&mbar_full[slot]);
                unsigned bh = bytes / 2;
                fence_async_smem();
                mbar_expect_tx(mb, bytes);
                bulk_g2s(sbase + slot * STAGE_BYTES,
                         gbase + (size_t)ns * STAGE_BYTES, bh, mb);
                bulk_g2s(sbase + slot * STAGE_BYTES + bh,
                         gbase + (size_t)ns * STAGE_BYTES + bh, bytes - bh, mb);
            }
            if (++slot == NSTAGES) { slot = 0; phase ^= 1; }
        }
    } else {
        // ================= LDG + bulk-prefetch path (R12) ==================
        const int npairs = rows_blk / 2;

        if (lane == 0) {
#pragma unroll
            for (int k = 0; k < AHEAD; k++) {
                int p = warp + k * WPB;
                if (p < npairs) {
                    int r = row_base + 2 * p;
                    bulk_prefetch_l2(embc + (size_t)r * ROWB, 2 * ROWB);
                }
            }
        }

        for (int p = warp; p < npairs; p += WPB) {
            if (lane == 0) {
                int pp = p + AHEAD * WPB;
                if (pp < npairs) {
                    int pr = row_base + 2 * pp;
                    bulk_prefetch_l2(embc + (size_t)pr * ROWB, 2 * ROWB);
                }
            }
            const int r0 = row_base + 2 * p;
            float s0, s1;
            dot2(emb4 + (size_t)r0 * DIM4, emb4 + (size_t)(r0 + 1) * DIM4,
                 lane, b0, b1, b2, s0, s1);
            if (lane == 0) {
                topk_insert(vals, ids, K, s0, r0);
                topk_insert(vals, ids, K, s1, r0 + 1);
            }
        }
        if (warp == 0 && (rows_blk & 1)) {
            const int r = row_end - 1;
            float acc = warp_sum(dot_row(emb4 + (size_t)r * DIM4, lane, b0, b1, b2));
            if (lane == 0) topk_insert(vals, ids, K, acc, r);
        }
    }

    // --- phase 2: block merge -> per-block candidates in gmem ---
    if (lane == 0) {
#pragma unroll
        for (int j = 0; j < MAXK; j++) {
            if (j < K) { sv[warp * K + j] = vals[j]; si[warp * K + j] = ids[j]; }
        }
    }
    __syncthreads();

    if (warp == 0) {
        float v2[MAXK];
        int   i2[MAXK];
#pragma unroll
        for (int j = 0; j < MAXK; j++) { v2[j] = -FLT_MAX; i2[j] = 0x7fffffff; }
        for (int e = lane; e < WPB * K; e += 32)
            topk_insert(v2, i2, K, sv[e], si[e]);

        float* gv = g_cand_v + (size_t)blockIdx.x * K;
        int*   gi = g_cand_i + (size_t)blockIdx.x * K;
        WARP_EXTRACT_TOPK(v2, i2, K, { gv[r] = bv; gi[r] = bid; });
    }

    // --- phase 3: last block to finish does the final merge ---
    __threadfence();
    if (tid == 0) {
        unsigned int prev = atomicAdd(&g_done, 1u);
        s_last = (prev == gridDim.x - 1) ? 1 : 0;
    }
    __syncthreads();
    if (!s_last) return;

    {
        const int NC = gridDim.x * K;
        float v3[MAXK];
        int   i3[MAXK];
#pragma unroll
        for (int j = 0; j < MAXK; j++) { v3[j] = -FLT_MAX; i3[j] = 0x7fffffff; }
        for (int e = tid; e < NC; e += TPB)
            topk_insert(v3, i3, K, g_cand_v[e], g_cand_i[e]);

        WARP_EXTRACT_TOPK(v3, i3, K, { sv[warp * K + r] = bv; si[warp * K + r] = bid; });
        __syncthreads();

        if (warp == 0) {
            float v4[MAXK];
            int   i4[MAXK];
#pragma unroll
            for (int j = 0; j < MAXK; j++) { v4[j] = -FLT_MAX; i4[j] = 0x7fffffff; }
            for (int e = lane; e < WPB * K; e += 32)
                topk_insert(v4, i4, K, sv[e], si[e]);

            WARP_EXTRACT_TOPK(v4, i4, K, {
                out[r]     = bv;
                out[K + r] = (float)bid;
            });
        }

        __syncthreads();
        if (tid == 0) g_done = 0;   // reset for deterministic graph replay
    }
}

// ---------------------------------------------------------------------------
// kernel_launch — single fused persistent kernel (2 CTAs/SM, one per path).
// Inputs: wordid int32 [1], embedding float32 [V*300], topk int32 [1].
// Output: float32 [2K]: K values then K indices (K = topk+1 = out_size/2).
// ---------------------------------------------------------------------------
extern "C" void kernel_launch(void* const* d_in, const int* in_sizes, int n_in,
                              void* d_out, int out_size)
{
    const int*   wordid = (const int*)d_in[0];
    const float* emb    = (const float*)d_in[1];

    int V = in_sizes[1] / DIM;       // 200000
    int K = out_size / 2;            // 11
    if (K > MAXK) K = MAXK;

    cudaFuncSetAttribute(fused_sim_topk_kernel,
                         cudaFuncAttributeMaxDynamicSharedMemorySize,
                         SMEM_BYTES);

    fused_sim_topk_kernel<<<NB, TPB, SMEM_BYTES>>>(wordid, emb,
                                                   (float*)d_out, V, K);
}

// round 17
// speedup vs baseline: 1.5564x; 1.5564x over previous
#include <cuda_runtime.h>
#include <cuda_bf16.h>
#include <float.h>
#include <stdint.h>

#define DIM     300
#define DIM4    75            // float4 per row
#define ROWB    (DIM * 4)     // 1200 bytes per row
#define MAXK    16
#define TPB     512           // 16 warps
#define WPB     (TPB / 32)
#define NB      296           // 2 blocks per SM -> 32 warps/SM
#define AHEAD   3             // prefetch lead in pair-iterations
                              // L2 lead footprint: 3*2.4KB*16w*296b ~= 34MB

// Scratch (allocation-free rule: __device__ globals)
__device__ float        g_cand_v[NB * MAXK];
__device__ int          g_cand_i[NB * MAXK];
__device__ unsigned int g_done = 0;

// ---------------------------------------------------------------------------
// PTX helpers
// ---------------------------------------------------------------------------
// Bulk prefetch into L2 via the TMA engine — fire-and-forget, no mbarrier,
// no LSU/MSHR tracking on the SM side.
__device__ __forceinline__ void bulk_prefetch_l2(const void* src, unsigned bytes)
{
    asm volatile("cp.async.bulk.prefetch.L2.global [%0], %1;"
                 :: "l"(src), "r"(bytes) : "memory");
}

// ---------------------------------------------------------------------------
// top-K helpers (ascending-sorted register list; slot 0 = current min)
// ---------------------------------------------------------------------------
__device__ __forceinline__ void topk_insert(float* vals, int* ids, int K,
                                            float s, int id)
{
    if (s > vals[0] || (s == vals[0] && id < ids[0])) {
        int j = 0;
        while (j < K - 1 &&
               (s > vals[j + 1] || (s == vals[j + 1] && id < ids[j + 1]))) {
            vals[j] = vals[j + 1];
            ids [j] = ids [j + 1];
            j++;
        }
        vals[j] = s;
        ids [j] = id;
    }
}

#define WARP_EXTRACT_TOPK(vals, ids, K, EMIT)                                  \
    do {                                                                       \
        int ptr = (K) - 1;                                                     \
        for (int r = 0; r < (K); r++) {                                        \
            float v  = (ptr >= 0) ? (vals)[ptr] : -FLT_MAX;                    \
            int   id = (ptr >= 0) ? (ids)[ptr]  : 0x7fffffff;                  \
            float bv = v; int bid = id; int bl = lane;                         \
            _Pragma("unroll")                                                  \
            for (int off = 16; off; off >>= 1) {                               \
                float ov  = __shfl_xor_sync(0xffffffffu, bv,  off);            \
                int   oid = __shfl_xor_sync(0xffffffffu, bid, off);            \
                int   ol  = __shfl_xor_sync(0xffffffffu, bl,  off);            \
                if (ov > bv || (ov == bv && oid < bid)) {                      \
                    bv = ov; bid = oid; bl = ol;                               \
                }                                                              \
            }                                                                  \
            if (lane == bl) ptr--;                                             \
            if (lane == 0) { EMIT; }                                           \
        }                                                                      \
    } while (0)

__device__ __forceinline__ float dot_row(const float4* __restrict__ rp,
                                         int lane,
                                         float4 b0, float4 b1, float4 b2)
{
    float4 a0 = rp[lane];
    float4 a1 = rp[lane + 32];
    float acc = a0.x * b0.x + a0.y * b0.y + a0.z * b0.z + a0.w * b0.w
              + a1.x * b1.x + a1.y * b1.y + a1.z * b1.z + a1.w * b1.w;
    if (lane < DIM4 - 64) {
        float4 a2 = rp[lane + 64];
        acc += a2.x * b2.x + a2.y * b2.y + a2.z * b2.z + a2.w * b2.w;
    }
    return acc;
}
__device__ __forceinline__ float warp_sum(float acc)
{
#pragma unroll
    for (int off = 16; off; off >>= 1)
        acc += __shfl_xor_sync(0xffffffffu, acc, off);
    return acc;
}
// two adjacent rows with interleaved reduction chains (6 LDG.128 in flight)
__device__ __forceinline__ void dot2(const float4* __restrict__ r0p,
                                     const float4* __restrict__ r1p,
                                     int lane, float4 b0, float4 b1, float4 b2,
                                     float& s0, float& s1)
{
    float4 a0 = r0p[lane],      a1 = r1p[lane];
    float4 c0 = r0p[lane + 32], c1 = r1p[lane + 32];
    s0 = a0.x*b0.x + a0.y*b0.y + a0.z*b0.z + a0.w*b0.w
       + c0.x*b1.x + c0.y*b1.y + c0.z*b1.z + c0.w*b1.w;
    s1 = a1.x*b0.x + a1.y*b0.y + a1.z*b0.z + a1.w*b0.w
       + c1.x*b1.x + c1.y*b1.y + c1.z*b1.z + c1.w*b1.w;
    if (lane < DIM4 - 64) {
        float4 d0 = r0p[lane + 64], d1 = r1p[lane + 64];
        s0 += d0.x*b2.x + d0.y*b2.y + d0.z*b2.z + d0.w*b2.w;
        s1 += d1.x*b2.x + d1.y*b2.y + d1.z*b2.z + d1.w*b2.w;
    }
#pragma unroll
    for (int off = 16; off; off >>= 1) {
        s0 += __shfl_xor_sync(0xffffffffu, s0, off);
        s1 += __shfl_xor_sync(0xffffffffu, s1, off);
    }
}

// ---------------------------------------------------------------------------
// Fused persistent kernel: LDG demand + TMA bulk-prefetch-to-L2 pacing
// + hierarchical top-K.  No smem ring, no mbarriers, no loop barriers.
// ---------------------------------------------------------------------------
__global__ void __launch_bounds__(TPB, 2)
fused_sim_topk_kernel(const int* __restrict__ wordid,
                      const float* __restrict__ emb,
                      float* __restrict__ out,
                      int V, int K)
{
    __shared__ float4 swv[DIM4];
    __shared__ float  sv[WPB * MAXK];
    __shared__ int    si[WPB * MAXK];
    __shared__ int    s_last;

    const int tid  = threadIdx.x;
    const int lane = tid & 31;
    const int warp = tid >> 5;

    {
        int w = wordid[0];
        if (tid < DIM4)
            swv[tid] = reinterpret_cast<const float4*>(emb + (size_t)w * DIM)[tid];
    }
    __syncthreads();

    const float4 b0 = swv[lane];
    const float4 b1 = swv[lane + 32];
    const float4 b2 = (lane < DIM4 - 64) ? swv[lane + 64]
                                         : make_float4(0.f, 0.f, 0.f, 0.f);

    // --- this block's contiguous row chunk ---
    const int chunk    = (V + NB - 1) / NB;
    const int row_base = blockIdx.x * chunk;
    int rows_blk = V - row_base;
    if (rows_blk > chunk) rows_blk = chunk;
    if (rows_blk < 0)     rows_blk = 0;
    const int row_end = row_base + rows_blk;
    const int npairs  = rows_blk / 2;             // adjacent-row pairs

    const float4* emb4  = reinterpret_cast<const float4*>(emb);
    const char*   embc  = reinterpret_cast<const char*>(emb);

    // --- per-warp running top-K (lane 0 holds it) ---
    float vals[MAXK];
    int   ids [MAXK];
#pragma unroll
    for (int j = 0; j < MAXK; j++) { vals[j] = -FLT_MAX; ids[j] = 0x7fffffff; }

    // --- prologue: each warp bulk-prefetches its first AHEAD iterations ---
    if (lane == 0) {
#pragma unroll
        for (int k = 0; k < AHEAD; k++) {
            int p = warp + k * WPB;
            if (p < npairs) {
                int r = row_base + 2 * p;
                bulk_prefetch_l2(embc + (size_t)r * ROWB, 2 * ROWB);
            }
        }
    }

    // --- main loop: warp-strided over adjacent-row pairs ---
    for (int p = warp; p < npairs; p += WPB) {
        // self-prefetch the pair AHEAD iterations ahead (TMA engine, no MSHR)
        if (lane == 0) {
            int pp = p + AHEAD * WPB;
            if (pp < npairs) {
                int pr = row_base + 2 * pp;
                bulk_prefetch_l2(embc + (size_t)pr * ROWB, 2 * ROWB);
            }
        }

        const int r0 = row_base + 2 * p;
        float s0, s1;
        dot2(emb4 + (size_t)r0 * DIM4, emb4 + (size_t)(r0 + 1) * DIM4,
             lane, b0, b1, b2, s0, s1);
        if (lane == 0) {
            topk_insert(vals, ids, K, s0, r0);
            topk_insert(vals, ids, K, s1, r0 + 1);
        }
    }

    // --- odd tail row (at most 1), warp 0 ---
    if (warp == 0 && (rows_blk & 1)) {
        const int r = row_end - 1;
        float acc = warp_sum(dot_row(emb4 + (size_t)r * DIM4, lane, b0, b1, b2));
        if (lane == 0) topk_insert(vals, ids, K, acc, r);
    }

    // --- phase 2: block merge -> per-block candidates in gmem ---
    if (lane == 0) {
#pragma unroll
        for (int j = 0; j < MAXK; j++) {
            if (j < K) { sv[warp * K + j] = vals[j]; si[warp * K + j] = ids[j]; }
        }
    }
    __syncthreads();

    if (warp == 0) {
        float v2[MAXK];
        int   i2[MAXK];
#pragma unroll
        for (int j = 0; j < MAXK; j++) { v2[j] = -FLT_MAX; i2[j] = 0x7fffffff; }
        for (int e = lane; e < WPB * K; e += 32)
            topk_insert(v2, i2, K, sv[e], si[e]);

        float* gv = g_cand_v + (size_t)blockIdx.x * K;
        int*   gi = g_cand_i + (size_t)blockIdx.x * K;
        WARP_EXTRACT_TOPK(v2, i2, K, { gv[r] = bv; gi[r] = bid; });
    }

    // --- phase 3: last block to finish does the final merge ---
    __threadfence();
    if (tid == 0) {
        unsigned int prev = atomicAdd(&g_done, 1u);
        s_last = (prev == gridDim.x - 1) ? 1 : 0;
    }
    __syncthreads();
    if (!s_last) return;

    {
        const int NC = gridDim.x * K;
        float v3[MAXK];
        int   i3[MAXK];
#pragma unroll
        for (int j = 0; j < MAXK; j++) { v3[j] = -FLT_MAX; i3[j] = 0x7fffffff; }
        for (int e = tid; e < NC; e += TPB)
            topk_insert(v3, i3, K, g_cand_v[e], g_cand_i[e]);

        WARP_EXTRACT_TOPK(v3, i3, K, { sv[warp * K + r] = bv; si[warp * K + r] = bid; });
        __syncthreads();

        if (warp == 0) {
            float v4[MAXK];
            int   i4[MAXK];
#pragma unroll
            for (int j = 0; j < MAXK; j++) { v4[j] = -FLT_MAX; i4[j] = 0x7fffffff; }
            for (int e = lane; e < WPB * K; e += 32)
                topk_insert(v4, i4, K, sv[e], si[e]);

            WARP_EXTRACT_TOPK(v4, i4, K, {
                out[r]     = bv;
                out[K + r] = (float)bid;
            });
        }

        __syncthreads();
        if (tid == 0) g_done = 0;   // reset for deterministic graph replay
    }
}

// ---------------------------------------------------------------------------
// kernel_launch — single fused persistent kernel (2 CTAs per SM).
// Inputs: wordid int32 [1], embedding float32 [V*300], topk int32 [1].
// Output: float32 [2K]: K values then K indices (K = topk+1 = out_size/2).
// ---------------------------------------------------------------------------
extern "C" void kernel_launch(void* const* d_in, const int* in_sizes, int n_in,
                              void* d_out, int out_size)
{
    const int*   wordid = (const int*)d_in[0];
    const float* emb    = (const float*)d_in[1];

    int V = in_sizes[1] / DIM;       // 200000
    int K = out_size / 2;            // 11
    if (K > MAXK) K = MAXK;

    fused_sim_topk_kernel<<<NB, TPB>>>(wordid, emb, (float*)d_out, V, K);
}